// round 9
// baseline (speedup 1.0000x reference)
#include <cuda_runtime.h>
#include <cuda_fp16.h>
#include <mma.h>
using namespace nvcuda;

// Problem constants
#define NN    25000
#define NPAD  25088          // multiple of 256; NPAD*16 == 1568*256 exactly
#define EE    400000
#define FN    32
#define FE    16
#define HH    16
#define MM    16
#define MPITERS 3

// ---------------- scratch (device globals) ---------------------------------
__device__ __align__(16) float  g_hidden [NPAD * HH];
__device__ __align__(16) float  g_hidden0[NPAD * HH];
__device__ __align__(16) __half g_Th     [NPAD * FE * MM];  // T2[n][m*16+f]
__device__ __align__(16) float  g_bb     [NPAD * MM];
__device__ __align__(16) float  g_msg    [NPAD * MM];
__device__ __align__(16) __half g_B16    [16 * 272];  // B[h][c]; c<256:(m=c>>4,f=c&15)->We[f*256+m*16+h]; c>=256: be[(c-256)*16+h]
__device__ int    g_count  [NPAD];            // invariant: 0 at kernel_launch entry
__device__ int    g_cursor [NPAD];
__device__ __align__(16) int4 g_pack [EE];    // {orig_e, sender, receiver, 0} sender-sorted

// ---------------- helpers ---------------------------------------------------
__device__ __forceinline__ unsigned long long pk2(float lo, float hi) {
    unsigned long long d;
    asm("mov.b64 %0, {%1, %2};" : "=l"(d) : "r"(__float_as_uint(lo)), "r"(__float_as_uint(hi)));
    return d;
}
__device__ __forceinline__ unsigned long long fma2(unsigned long long a,
                                                   unsigned long long b,
                                                   unsigned long long c) {
    unsigned long long d;
    asm("fma.rn.f32x2 %0, %1, %2, %3;" : "=l"(d) : "l"(a), "l"(b), "l"(c));
    return d;
}
__device__ __forceinline__ float upk_sum(unsigned long long v) {
    unsigned int a, b;
    asm("mov.b64 {%0, %1}, %2;" : "=r"(a), "=r"(b) : "l"(v));
    return __uint_as_float(a) + __uint_as_float(b);
}
__device__ __forceinline__ unsigned int h2_as_u32(__half2 h) {
    return *reinterpret_cast<unsigned int*>(&h);
}
__device__ __forceinline__ float tanh_fast(float x) {
    float r;
    asm("tanh.approx.f32 %0, %1;" : "=f"(r) : "f"(x));
    return r;
}
__device__ __forceinline__ float sigmoid_fast(float x) {
    return fmaf(0.5f, tanh_fast(0.5f * x), 0.5f);
}
__device__ __forceinline__ float dot4(float4 a, float4 b) {
    float r = a.x * b.x;
    r = fmaf(a.y, b.y, r);
    r = fmaf(a.z, b.z, r);
    r = fmaf(a.w, b.w, r);
    return r;
}

// ---------------- kernel 1: init hidden + hist + zero msg/out --------------
__global__ __launch_bounds__(256)
void init_kernel(const float* __restrict__ nf, const float* __restrict__ Wi,
                 const float* __restrict__ bi, const int* __restrict__ send,
                 float* __restrict__ out) {
    __shared__ float Wsh[FN * HH];
    int tid = threadIdx.x;
    int gid = blockIdx.x * 256 + tid;

    if (gid < EE) atomicAdd(&g_count[send[gid]], 1);   // g_count==0 at entry
    g_msg[gid] = 0.f;                                   // grid*256 == NPAD*16
    if (gid == 0) out[0] = 0.f;

    int j  = tid & 15;
    int nl = tid >> 4;
    int n  = blockIdx.x * 16 + nl;
    for (int idx = tid; idx < FN * HH; idx += 256) Wsh[idx] = Wi[idx];
    __syncthreads();

    int nr = (n < NN) ? n : (NN - 1);
    const float* row = nf + (long)nr * FN;
    float acc = bi[j];
#pragma unroll
    for (int f = 0; f < FN; f++) acc = fmaf(row[f], Wsh[f * 16 + j], acc);
    g_hidden [n * 16 + j] = acc;
    g_hidden0[n * 16 + j] = acc;
}

// ---------------- scan: prefix sum + re-zero count + build B16 -------------
__global__ __launch_bounds__(1024)
void scan_kernel(const float* __restrict__ We, const float* __restrict__ be) {
    __shared__ int sh[1024];
    int t = threadIdx.x;

    for (int idx = t; idx < 16 * 272; idx += 1024) {
        int h = idx / 272, c = idx % 272;
        float v = (c < 256) ? We[(c & 15) * 256 + (c >> 4) * 16 + h]
                            : be[(c - 256) * 16 + h];
        g_B16[idx] = __float2half_rn(v);
    }

    int vals[25];
    int sum = 0;
    int base = t * 25;
#pragma unroll
    for (int k = 0; k < 25; k++) {
        int idx = base + k;
        int v = (idx < NPAD) ? g_count[idx] : 0;
        vals[k] = v; sum += v;
    }
    sh[t] = sum;
    __syncthreads();
    for (int off = 1; off < 1024; off <<= 1) {
        int v = (t >= off) ? sh[t - off] : 0;
        __syncthreads();
        sh[t] += v;
        __syncthreads();
    }
    int ex = (t == 0) ? 0 : sh[t - 1];
#pragma unroll
    for (int k = 0; k < 25; k++) {
        int idx = base + k;
        if (idx < NPAD) { g_cursor[idx] = ex; ex += vals[k]; g_count[idx] = 0; }
    }
}

// ---------------- scatter: build sorted packed edge records ----------------
__global__ __launch_bounds__(256)
void scatter_kernel(const int* __restrict__ send, const int* __restrict__ recv) {
    int e = blockIdx.x * 256 + threadIdx.x;
    if (e < EE) {
        int s = send[e];
        int r = recv[e];
        int p = atomicAdd(&g_cursor[s], 1);
        g_pack[p] = make_int4(e, s, r, 0);
    }
}

// ---------------- kernel 2: T/bb via tensor cores, v2 ----------------------
// 256 threads = 8 warps; block covers 256 nodes (2 tiles/warp). B staged in
// shared once; fp32 accumulators; T written as packed half uint4 stores.
__global__ __launch_bounds__(256)
void t_mma_kernel() {
    __shared__ __align__(16) __half shB[16 * 272];          // 8704 B
    __shared__ __align__(16) __half shA[8][2][256];         // 8192 B
    __shared__ __align__(16) float  shT[8][2][256];         // 16384 B

    int tid = threadIdx.x, w = tid >> 5, lane = tid & 31;
    int nbase = blockIdx.x * 256 + w * 32;

    // stage B (coalesced)
    for (int idx = tid; idx < 544; idx += 256)
        ((uint4*)shB)[idx] = ((const uint4*)g_B16)[idx];

    // stage A: 512 floats per warp (32 nodes x 16 h), coalesced 128B per step
    for (int idx = lane; idx < 512; idx += 32)
        shA[w][idx >> 8][idx & 255] =
            __float2half_rn(g_hidden[(long)nbase * 16 + idx]);
    __syncthreads();

    wmma::fragment<wmma::matrix_a, 16, 16, 16, __half, wmma::row_major> fa0, fa1;
    wmma::load_matrix_sync(fa0, shA[w][0], 16);
    wmma::load_matrix_sync(fa1, shA[w][1], 16);

#pragma unroll 1
    for (int j = 0; j < 17; j++) {
        wmma::fragment<wmma::matrix_b, 16, 16, 16, __half, wmma::row_major> fb;
        wmma::load_matrix_sync(fb, shB + j * 16, 272);
        wmma::fragment<wmma::accumulator, 16, 16, 16, float> fc0, fc1;
        wmma::fill_fragment(fc0, 0.f);
        wmma::fill_fragment(fc1, 0.f);
        wmma::mma_sync(fc0, fa0, fb, fc0);
        wmma::mma_sync(fc1, fa1, fb, fc1);
        wmma::store_matrix_sync(shT[w][0], fc0, 16, wmma::mem_row_major);
        wmma::store_matrix_sync(shT[w][1], fc1, 16, wmma::mem_row_major);
        __syncwarp();
        if (j < 16) {
            // per lane: one 16B store of 8 halves per tile
            int nl = lane >> 1, q = lane & 1;
#pragma unroll
            for (int t = 0; t < 2; t++) {
                const float* src = &shT[w][t][nl * 16 + q * 8];
                float4 a = ((const float4*)src)[0];
                float4 b = ((const float4*)src)[1];
                __half2 h0 = __floats2half2_rn(a.x, a.y);
                __half2 h1 = __floats2half2_rn(a.z, a.w);
                __half2 h2 = __floats2half2_rn(b.x, b.y);
                __half2 h3 = __floats2half2_rn(b.z, b.w);
                uint4 pkv = make_uint4(h2_as_u32(h0), h2_as_u32(h1),
                                       h2_as_u32(h2), h2_as_u32(h3));
                int node = nbase + t * 16 + nl;
                *(uint4*)((char*)g_Th + (long)node * 512 + j * 32 + q * 16) = pkv;
            }
        } else {
            // bb: fp32, 2 tiles x 64 float4 -> 4 stores per lane
#pragma unroll
            for (int t = 0; t < 2; t++) {
                for (int idx = lane; idx < 64; idx += 32) {
                    int nl = idx >> 2, q = idx & 3;
                    float4 v = ((const float4*)&shT[w][t][nl * 16])[q];
                    ((float4*)(g_bb + (long)(nbase + t * 16 + nl) * 16))[q] = v;
                }
            }
        }
        __syncwarp();
    }
}

// ---------------- kernel 3: per-edge message (fp16 T, staged ef) -----------
__global__ __launch_bounds__(256)
void edge_kernel(const float* __restrict__ ef) {
    __shared__ int4 shPack[64];
    __shared__ __align__(16) float shEf[64][20];   // stride 80B: conflict-free

    int tid = threadIdx.x;
    int base = blockIdx.x * 64;
    if (tid < 64) shPack[tid] = g_pack[base + tid];
    __syncthreads();

    int le = tid >> 2, q = tid & 3;
    int e = shPack[le].x;
    ((float4*)shEf[le])[q] = ((const float4*)(ef + (long)e * 16))[q];
    int s = shPack[le].y;
    int r = shPack[le].z;
    int mg = q;

    const uint4* tp = (const uint4*)(g_Th + (long)s * 256);
    uint4 tv[8];
#pragma unroll
    for (int qq = 0; qq < 4; qq++) {
        tv[qq * 2]     = tp[(mg * 4 + qq) * 2];
        tv[qq * 2 + 1] = tp[(mg * 4 + qq) * 2 + 1];
    }
    float4 bbv = *(const float4*)(g_bb + s * 16 + mg * 4);
    float bbs[4] = {bbv.x, bbv.y, bbv.z, bbv.w};
    __syncthreads();

    unsigned long long wp[8];
#pragma unroll
    for (int k = 0; k < 8; k++)
        wp[k] = pk2(shEf[le][2 * k], shEf[le][2 * k + 1]);

    float outv[4];
#pragma unroll
    for (int qq = 0; qq < 4; qq++) {
        unsigned long long acc = pk2(bbs[qq], 0.f);
        const __half2* hh = (const __half2*)&tv[qq * 2];
#pragma unroll
        for (int k = 0; k < 8; k++) {
            float2 v = __half22float2(hh[k]);
            acc = fma2(pk2(v.x, v.y), wp[k], acc);
        }
        outv[qq] = upk_sum(acc);
    }
    float* dst = g_msg + r * 16 + mg * 4;
    asm volatile("red.global.add.v4.f32 [%0], {%1, %2, %3, %4};"
                 :: "l"(dst), "f"(outv[0]), "f"(outv[1]), "f"(outv[2]), "f"(outv[3])
                 : "memory");
}

// ---------------- kernel 4: GRU, 4 nodes per thread ------------------------
__global__ __launch_bounds__(256)
void gru_kernel(const float* __restrict__ Wi, const float* __restrict__ Wh,
                const float* __restrict__ bi, const float* __restrict__ bh) {
    __shared__ __align__(16) float sh_h[2][64][16];
    __shared__ float sh_seq[64][33];

    int tid = threadIdx.x;
    int j  = tid & 15;
    int sl = tid >> 4;
    int nbase = blockIdx.x * 64;

    unsigned long long wz[8], wr[8], wh[8];
#pragma unroll
    for (int k = 0; k < 8; k++) {
        wz[k] = pk2(Wh[(2 * k) * 48 + j],      Wh[(2 * k + 1) * 48 + j]);
        wr[k] = pk2(Wh[(2 * k) * 48 + 16 + j], Wh[(2 * k + 1) * 48 + 16 + j]);
        wh[k] = pk2(Wh[(2 * k) * 48 + 32 + j], Wh[(2 * k + 1) * 48 + 32 + j]);
    }
    float wiz = Wi[j], wir = Wi[16 + j], wih = Wi[32 + j];
    // fold input bias into recurrent bias for z and r (added pre-activation)
    float bz = bi[j]      + bh[j];
    float br = bi[16 + j] + bh[16 + j];
    float bih = bi[32 + j];
    float bhh = bh[32 + j];

    float h[4];
#pragma unroll
    for (int u = 0; u < 4; u++) {
        int row = sl + u * 16;
        int n = nbase + row;
        sh_seq[row][j]      = g_hidden[n * 16 + j];
        sh_seq[row][16 + j] = g_msg   [n * 16 + j];
        g_msg[n * 16 + j] = 0.f;          // re-zero for next iteration
        sh_h[0][row][j] = 0.f;
        h[u] = 0.f;
    }
    __syncthreads();

#pragma unroll 1
    for (int t = 0; t < 32; t++) {
        int cur = t & 1;
        float x[4];
        unsigned long long az[4], ar[4], ah[4];
#pragma unroll
        for (int u = 0; u < 4; u++) {
            x[u] = sh_seq[sl + u * 16][t];
            az[u] = pk2(bz, 0.f);
            ar[u] = pk2(br, 0.f);
            ah[u] = pk2(bhh, 0.f);
        }
#pragma unroll
        for (int k = 0; k < 4; k++) {
#pragma unroll
            for (int u = 0; u < 4; u++) {
                ulonglong2 p = ((const ulonglong2*)sh_h[cur][sl + u * 16])[k];
                az[u] = fma2(p.x, wz[2 * k],     az[u]);
                az[u] = fma2(p.y, wz[2 * k + 1], az[u]);
                ar[u] = fma2(p.x, wr[2 * k],     ar[u]);
                ar[u] = fma2(p.y, wr[2 * k + 1], ar[u]);
                ah[u] = fma2(p.x, wh[2 * k],     ah[u]);
                ah[u] = fma2(p.y, wh[2 * k + 1], ah[u]);
            }
        }
#pragma unroll
        for (int u = 0; u < 4; u++) {
            float ghz = upk_sum(az[u]), ghr = upk_sum(ar[u]), ghh = upk_sum(ah[u]);
            float z = sigmoid_fast(fmaf(x[u], wiz, ghz));
            float r = sigmoid_fast(fmaf(x[u], wir, ghr));
            float hc = tanh_fast(fmaf(x[u], wih, bih) + r * ghh);
            h[u] = hc + z * (h[u] - hc);
            sh_h[cur ^ 1][sl + u * 16][j] = h[u];
        }
        __syncwarp();
    }
#pragma unroll
    for (int u = 0; u < 4; u++)
        g_hidden[(nbase + sl + u * 16) * 16 + j] = h[u];
}

// ---------------- readout --------------------------------------------------
__global__ __launch_bounds__(256)
void readout_kernel(const float* __restrict__ Wri, const float* __restrict__ bri,
                    const float* __restrict__ Wrj, const float* __restrict__ brj,
                    float* __restrict__ out) {
    int n = blockIdx.x * 256 + threadIdx.x;
    float p = 0.f;
    if (n < NN) {
        const float4* hp  = (const float4*)(g_hidden  + n * 16);
        const float4* h0p = (const float4*)(g_hidden0 + n * 16);
        const float4* wi  = (const float4*)Wri;
        const float4* wj  = (const float4*)Wrj;
        float4 h0 = hp[0], h1 = hp[1], h2 = hp[2], h3 = hp[3];
        float4 g0 = h0p[0], g1 = h0p[1], g2 = h0p[2], g3 = h0p[3];
        float iv = bri[0]
                 + dot4(h0, wi[0]) + dot4(h1, wi[1]) + dot4(h2, wi[2]) + dot4(h3, wi[3])
                 + dot4(g0, wi[4]) + dot4(g1, wi[5]) + dot4(g2, wi[6]) + dot4(g3, wi[7]);
        float jv = brj[0]
                 + dot4(h0, wj[0]) + dot4(h1, wj[1]) + dot4(h2, wj[2]) + dot4(h3, wj[3]);
        p = iv * jv;
    }
#pragma unroll
    for (int off = 16; off > 0; off >>= 1)
        p += __shfl_down_sync(0xffffffffu, p, off);
    if ((threadIdx.x & 31) == 0) atomicAdd(out, p);
}

// ---------------- launch ---------------------------------------------------
extern "C" void kernel_launch(void* const* d_in, const int* in_sizes, int n_in,
                              void* d_out, int out_size) {
    const float* nf     = (const float*)d_in[0];
    const float* ef     = (const float*)d_in[1];
    const float* W_init = (const float*)d_in[2];
    const float* b_init = (const float*)d_in[3];
    const float* W_edge = (const float*)d_in[4];
    const float* b_edge = (const float*)d_in[5];
    const float* Wi_gru = (const float*)d_in[6];
    const float* Wh_gru = (const float*)d_in[7];
    const float* bi_gru = (const float*)d_in[8];
    const float* bh_gru = (const float*)d_in[9];
    const float* W_ri   = (const float*)d_in[10];
    const float* b_ri   = (const float*)d_in[11];
    const float* W_rj   = (const float*)d_in[12];
    const float* b_rj   = (const float*)d_in[13];
    const int*   recv   = (const int*)d_in[14];
    const int*   send   = (const int*)d_in[15];
    float* out = (float*)d_out;

    init_kernel<<<NPAD / 16, 256>>>(nf, W_init, b_init, send, out);
    scan_kernel<<<1, 1024>>>(W_edge, b_edge);
    scatter_kernel<<<(EE + 255) / 256, 256>>>(send, recv);

    for (int it = 0; it < MPITERS; it++) {
        t_mma_kernel<<<NPAD / 256, 256>>>();
        edge_kernel<<<EE / 64, 256>>>(ef);
        gru_kernel<<<NPAD / 64, 256>>>(Wi_gru, Wh_gru, bi_gru, bh_gru);
    }

    readout_kernel<<<(NN + 255) / 256, 256>>>(W_ri, b_ri, W_rj, b_rj, out);
}

// round 10
// speedup vs baseline: 1.1784x; 1.1784x over previous
#include <cuda_runtime.h>

// Problem constants
#define NN    25000
#define NPAD  25024          // multiple of 64; NPAD*16 == 1564*256 exactly
#define EE    400000
#define FN    32
#define FE    16
#define HH    16
#define MM    16
#define MPITERS 3

// ---------------- scratch (device globals) ---------------------------------
__device__ __align__(16) float g_hidden [NPAD * HH];
__device__ __align__(16) float g_hidden0[NPAD * HH];
__device__ __align__(16) float g_T      [NPAD * FE * MM];   // T[n][f*16+m]
__device__ __align__(16) float g_bb     [NPAD * MM];
__device__ __align__(16) float g_msg    [NPAD * MM];
__device__ int   g_count  [NPAD];
__device__ int   g_cursor [NPAD];
__device__ int   g_perm   [EE];
__device__ int   g_recvs  [EE];
__device__ int   g_sends  [EE];

// ---------------- f32x2 helpers -------------------------------------------
__device__ __forceinline__ unsigned long long pk2(float lo, float hi) {
    unsigned long long d;
    asm("mov.b64 %0, {%1, %2};" : "=l"(d) : "r"(__float_as_uint(lo)), "r"(__float_as_uint(hi)));
    return d;
}
__device__ __forceinline__ unsigned long long fma2(unsigned long long a,
                                                   unsigned long long b,
                                                   unsigned long long c) {
    unsigned long long d;
    asm("fma.rn.f32x2 %0, %1, %2, %3;" : "=l"(d) : "l"(a), "l"(b), "l"(c));
    return d;
}
__device__ __forceinline__ float upk_sum(unsigned long long v) {
    unsigned int a, b;
    asm("mov.b64 {%0, %1}, %2;" : "=r"(a), "=r"(b) : "l"(v));
    return __uint_as_float(a) + __uint_as_float(b);
}
__device__ __forceinline__ void upk(unsigned long long v, float& a, float& b) {
    unsigned int x, y;
    asm("mov.b64 {%0, %1}, %2;" : "=r"(x), "=r"(y) : "l"(v));
    a = __uint_as_float(x); b = __uint_as_float(y);
}
__device__ __forceinline__ float tanh_fast(float x) {
    float r;
    asm("tanh.approx.f32 %0, %1;" : "=f"(r) : "f"(x));
    return r;
}
__device__ __forceinline__ float sigmoid_fast(float x) {
    return fmaf(0.5f, tanh_fast(0.5f * x), 0.5f);
}
__device__ __forceinline__ float dot4(float4 a, float4 b) {
    float r = a.x * b.x;
    r = fmaf(a.y, b.y, r);
    r = fmaf(a.z, b.z, r);
    r = fmaf(a.w, b.w, r);
    return r;
}

// ---------------- kernel 1: init hidden + zero counters + zero out ---------
__global__ __launch_bounds__(256)
void init_kernel(const float* __restrict__ nf, const float* __restrict__ Wi,
                 const float* __restrict__ bi, float* __restrict__ out) {
    __shared__ float Wsh[FN * HH];
    int tid = threadIdx.x;
    int gid = blockIdx.x * 256 + tid;
    if (gid < NPAD) g_count[gid] = 0;
    if (gid == 0) out[0] = 0.f;

    int j  = tid & 15;
    int nl = tid >> 4;
    int n  = blockIdx.x * 16 + nl;            // grid = NPAD/16 -> n < NPAD always
    for (int idx = tid; idx < FN * HH; idx += 256) Wsh[idx] = Wi[idx];
    __syncthreads();
    int nr = (n < NN) ? n : (NN - 1);
    const float* row = nf + (long)nr * FN;
    float acc = bi[j];
#pragma unroll
    for (int f = 0; f < FN; f++) acc = fmaf(row[f], Wsh[f * 16 + j], acc);
    g_hidden [n * 16 + j] = acc;
    g_hidden0[n * 16 + j] = acc;
}

// ---------------- CSR build ------------------------------------------------
__global__ __launch_bounds__(256)
void hist_kernel(const int* __restrict__ send) {
    int e = blockIdx.x * 256 + threadIdx.x;
    if (e < EE) atomicAdd(&g_count[send[e]], 1);
}

__global__ __launch_bounds__(1024)
void scan_kernel() {
    __shared__ int sh[1024];
    int t = threadIdx.x;
    int vals[25];
    int sum = 0;
    int base = t * 25;
#pragma unroll
    for (int k = 0; k < 25; k++) {
        int idx = base + k;
        int v = (idx < NPAD) ? g_count[idx] : 0;
        vals[k] = v; sum += v;
    }
    sh[t] = sum;
    __syncthreads();
    for (int off = 1; off < 1024; off <<= 1) {
        int v = (t >= off) ? sh[t - off] : 0;
        __syncthreads();
        sh[t] += v;
        __syncthreads();
    }
    int ex = (t == 0) ? 0 : sh[t - 1];
#pragma unroll
    for (int k = 0; k < 25; k++) {
        int idx = base + k;
        if (idx < NPAD) { g_cursor[idx] = ex; ex += vals[k]; }
    }
}

__global__ __launch_bounds__(256)
void scatter_kernel(const int* __restrict__ send, const int* __restrict__ recv) {
    int e = blockIdx.x * 256 + threadIdx.x;
    if (e < EE) {
        int s = send[e];
        int r = recv[e];
        int p = atomicAdd(&g_cursor[s], 1);
        g_perm[p]  = e;
        g_sends[p] = s;
        g_recvs[p] = r;
    }
}

// ---------------- kernel 2: per-node T / bb (+ zero msg fused), f32x2 ------
// thread = (f = tid>>4, m = tid&15); W column pre-packed as 8 f32x2 pairs.
__global__ __launch_bounds__(256)
void t_kernel(const float* __restrict__ We, const float* __restrict__ be) {
    for (int idx = blockIdx.x * 256 + threadIdx.x; idx < NPAD * MM;
         idx += gridDim.x * 256)
        g_msg[idx] = 0.f;

    __shared__ __align__(16) float sh[64 * HH];
    int tid = threadIdx.x;
    int f = tid >> 4;
    int m = tid & 15;

    const float* wrow = We + (f * 256 + m * 16);
    unsigned long long w2[8];
#pragma unroll
    for (int k = 0; k < 8; k++) w2[k] = pk2(wrow[2 * k], wrow[2 * k + 1]);

    unsigned long long b2[8];
    if (f == 0) {
        const float* brow = be + m * 16;
#pragma unroll
        for (int k = 0; k < 8; k++) b2[k] = pk2(brow[2 * k], brow[2 * k + 1]);
    }

    int base = blockIdx.x * 64;
    int cnt = NN - base;
    if (cnt > 64) cnt = 64;
    if (cnt <= 0) return;

    for (int idx = tid; idx < cnt * HH; idx += 256)
        sh[idx] = g_hidden[base * HH + idx];
    __syncthreads();

#pragma unroll 2
    for (int nl = 0; nl < cnt; nl++) {
        const ulonglong2* hp = (const ulonglong2*)(sh + nl * HH);
        ulonglong2 hA = hp[0], hB = hp[1], hC = hp[2], hD = hp[3];
        unsigned long long acc = fma2(hA.x, w2[0], pk2(0.f, 0.f));
        acc = fma2(hA.y, w2[1], acc);
        acc = fma2(hB.x, w2[2], acc);
        acc = fma2(hB.y, w2[3], acc);
        acc = fma2(hC.x, w2[4], acc);
        acc = fma2(hC.y, w2[5], acc);
        acc = fma2(hD.x, w2[6], acc);
        acc = fma2(hD.y, w2[7], acc);
        g_T[(long)(base + nl) * 256 + tid] = upk_sum(acc);
        if (f == 0) {
            unsigned long long bacc = fma2(hA.x, b2[0], pk2(0.f, 0.f));
            bacc = fma2(hA.y, b2[1], bacc);
            bacc = fma2(hB.x, b2[2], bacc);
            bacc = fma2(hB.y, b2[3], bacc);
            bacc = fma2(hC.x, b2[4], bacc);
            bacc = fma2(hC.y, b2[5], bacc);
            bacc = fma2(hD.x, b2[6], bacc);
            bacc = fma2(hD.y, b2[7], bacc);
            g_bb[(base + nl) * 16 + m] = upk_sum(bacc);
        }
    }
}

// ---------------- kernel 3: per-edge message, batched fp32 loads -----------
// 4 threads/edge (mg = m-quad). All 16 T loads issued into a register array
// BEFORE the fma chain -> MLP ~16, hides L1/L2 latency.
__global__ __launch_bounds__(256)
void edge_kernel(const float* __restrict__ ef) {
    int tid = threadIdx.x;
    int i  = blockIdx.x * 64 + (tid >> 2);
    int mg = tid & 3;

    int s = g_sends[i];
    int e = g_perm[i];
    int r = g_recvs[i];

    const float4* ep = (const float4*)(ef + (long)e * 16);
    float4 e0 = ep[0];
    float4 e1 = ep[1];
    float4 e2 = ep[2];
    float4 e3 = ep[3];

    const ulonglong2* Tb = (const ulonglong2*)(g_T + (long)s * 256) + mg;
    ulonglong2 tv[16];
#pragma unroll
    for (int F = 0; F < 16; F++) tv[F] = Tb[F * 4];

    float4 bbv = *(const float4*)(g_bb + s * 16 + mg * 4);
    unsigned long long accL = pk2(bbv.x, bbv.y);
    unsigned long long accH = pk2(bbv.z, bbv.w);

    float w[16] = {e0.x, e0.y, e0.z, e0.w, e1.x, e1.y, e1.z, e1.w,
                   e2.x, e2.y, e2.z, e2.w, e3.x, e3.y, e3.z, e3.w};
#pragma unroll
    for (int F = 0; F < 16; F++) {
        unsigned long long ww = pk2(w[F], w[F]);
        accL = fma2(tv[F].x, ww, accL);
        accH = fma2(tv[F].y, ww, accH);
    }

    float r0, r1, r2, r3;
    upk(accL, r0, r1);
    upk(accH, r2, r3);
    float* dst = g_msg + r * 16 + mg * 4;
    asm volatile("red.global.add.v4.f32 [%0], {%1, %2, %3, %4};"
                 :: "l"(dst), "f"(r0), "f"(r1), "f"(r2), "f"(r3) : "memory");
}

// ---------------- kernel 4: GRU, 4 nodes per thread ------------------------
__global__ __launch_bounds__(256)
void gru_kernel(const float* __restrict__ Wi, const float* __restrict__ Wh,
                const float* __restrict__ bi, const float* __restrict__ bh) {
    __shared__ __align__(16) float sh_h[2][64][16];
    __shared__ float sh_seq[64][33];

    int tid = threadIdx.x;
    int j  = tid & 15;
    int sl = tid >> 4;
    int nbase = blockIdx.x * 64;

    unsigned long long wz[8], wr[8], wh[8];
#pragma unroll
    for (int k = 0; k < 8; k++) {
        wz[k] = pk2(Wh[(2 * k) * 48 + j],      Wh[(2 * k + 1) * 48 + j]);
        wr[k] = pk2(Wh[(2 * k) * 48 + 16 + j], Wh[(2 * k + 1) * 48 + 16 + j]);
        wh[k] = pk2(Wh[(2 * k) * 48 + 32 + j], Wh[(2 * k + 1) * 48 + 32 + j]);
    }
    float wiz = Wi[j], wir = Wi[16 + j], wih = Wi[32 + j];
    float biz = bi[j], bir = bi[16 + j], bih = bi[32 + j];
    float bhz = bh[j], bhr = bh[16 + j], bhh = bh[32 + j];

    float h[4];
#pragma unroll
    for (int u = 0; u < 4; u++) {
        int row = sl + u * 16;
        int n = nbase + row;
        sh_seq[row][j]      = g_hidden[n * 16 + j];
        sh_seq[row][16 + j] = g_msg   [n * 16 + j];
        sh_h[0][row][j] = 0.f;
        h[u] = 0.f;
    }
    __syncthreads();

#pragma unroll 1
    for (int t = 0; t < 32; t++) {
        int cur = t & 1;
        float x[4];
        unsigned long long az[4], ar[4], ah[4];
#pragma unroll
        for (int u = 0; u < 4; u++) {
            x[u] = sh_seq[sl + u * 16][t];
            az[u] = pk2(bhz, 0.f);
            ar[u] = pk2(bhr, 0.f);
            ah[u] = pk2(bhh, 0.f);
        }
#pragma unroll
        for (int k = 0; k < 4; k++) {
#pragma unroll
            for (int u = 0; u < 4; u++) {
                ulonglong2 p = ((const ulonglong2*)sh_h[cur][sl + u * 16])[k];
                az[u] = fma2(p.x, wz[2 * k],     az[u]);
                az[u] = fma2(p.y, wz[2 * k + 1], az[u]);
                ar[u] = fma2(p.x, wr[2 * k],     ar[u]);
                ar[u] = fma2(p.y, wr[2 * k + 1], ar[u]);
                ah[u] = fma2(p.x, wh[2 * k],     ah[u]);
                ah[u] = fma2(p.y, wh[2 * k + 1], ah[u]);
            }
        }
#pragma unroll
        for (int u = 0; u < 4; u++) {
            float ghz = upk_sum(az[u]), ghr = upk_sum(ar[u]), ghh = upk_sum(ah[u]);
            float z = sigmoid_fast(fmaf(x[u], wiz, biz) + ghz);
            float r = sigmoid_fast(fmaf(x[u], wir, bir) + ghr);
            float hc = tanh_fast(fmaf(x[u], wih, bih) + r * ghh);
            h[u] = hc + z * (h[u] - hc);
            sh_h[cur ^ 1][sl + u * 16][j] = h[u];
        }
        __syncwarp();
    }
#pragma unroll
    for (int u = 0; u < 4; u++)
        g_hidden[(nbase + sl + u * 16) * 16 + j] = h[u];
}

// ---------------- readout --------------------------------------------------
__global__ __launch_bounds__(256)
void readout_kernel(const float* __restrict__ Wri, const float* __restrict__ bri,
                    const float* __restrict__ Wrj, const float* __restrict__ brj,
                    float* __restrict__ out) {
    int n = blockIdx.x * 256 + threadIdx.x;
    float p = 0.f;
    if (n < NN) {
        const float4* hp  = (const float4*)(g_hidden  + n * 16);
        const float4* h0p = (const float4*)(g_hidden0 + n * 16);
        const float4* wi  = (const float4*)Wri;
        const float4* wj  = (const float4*)Wrj;
        float4 h0 = hp[0], h1 = hp[1], h2 = hp[2], h3 = hp[3];
        float4 g0 = h0p[0], g1 = h0p[1], g2 = h0p[2], g3 = h0p[3];
        float iv = bri[0]
                 + dot4(h0, wi[0]) + dot4(h1, wi[1]) + dot4(h2, wi[2]) + dot4(h3, wi[3])
                 + dot4(g0, wi[4]) + dot4(g1, wi[5]) + dot4(g2, wi[6]) + dot4(g3, wi[7]);
        float jv = brj[0]
                 + dot4(h0, wj[0]) + dot4(h1, wj[1]) + dot4(h2, wj[2]) + dot4(h3, wj[3]);
        p = iv * jv;
    }
#pragma unroll
    for (int off = 16; off > 0; off >>= 1)
        p += __shfl_down_sync(0xffffffffu, p, off);
    if ((threadIdx.x & 31) == 0) atomicAdd(out, p);
}

// ---------------- launch ---------------------------------------------------
extern "C" void kernel_launch(void* const* d_in, const int* in_sizes, int n_in,
                              void* d_out, int out_size) {
    const float* nf     = (const float*)d_in[0];
    const float* ef     = (const float*)d_in[1];
    const float* W_init = (const float*)d_in[2];
    const float* b_init = (const float*)d_in[3];
    const float* W_edge = (const float*)d_in[4];
    const float* b_edge = (const float*)d_in[5];
    const float* Wi_gru = (const float*)d_in[6];
    const float* Wh_gru = (const float*)d_in[7];
    const float* bi_gru = (const float*)d_in[8];
    const float* bh_gru = (const float*)d_in[9];
    const float* W_ri   = (const float*)d_in[10];
    const float* b_ri   = (const float*)d_in[11];
    const float* W_rj   = (const float*)d_in[12];
    const float* b_rj   = (const float*)d_in[13];
    const int*   recv   = (const int*)d_in[14];
    const int*   send   = (const int*)d_in[15];
    float* out = (float*)d_out;

    init_kernel<<<NPAD / 16, 256>>>(nf, W_init, b_init, out);
    hist_kernel<<<(EE + 255) / 256, 256>>>(send);
    scan_kernel<<<1, 1024>>>();
    scatter_kernel<<<(EE + 255) / 256, 256>>>(send, recv);

    for (int it = 0; it < MPITERS; it++) {
        t_kernel<<<(NN + 63) / 64, 256>>>(W_edge, b_edge);
        edge_kernel<<<EE / 64, 256>>>(ef);
        gru_kernel<<<NPAD / 64, 256>>>(Wi_gru, Wh_gru, bi_gru, bh_gru);
    }

    readout_kernel<<<(NN + 255) / 256, 256>>>(W_ri, b_ri, W_rj, b_rj, out);
}